// round 14
// baseline (speedup 1.0000x reference)
#include <cuda_runtime.h>
#include <cuda_bf16.h>
#include <math.h>
#include <stdint.h>

// Problem constants
#define Bn    8
#define Tn    2048
#define Dn    1024
#define DSn   256
#define KLn   32
#define WINn  3
#define Mtot  (Bn * Tn)      // 16384
// SCALE = sqrt(DS) = 16

// Scratch
__device__ float g_Q[Mtot * DSn];                    // 16 MB
__device__ float g_K[Mtot * DSn];                    // 16 MB
__device__ float g_P[Mtot * KLn];                    // 2 MB:  P = h @ Wp
__device__ __nv_bfloat16 g_Xhi[Mtot * Dn];           // 32 MB
__device__ __nv_bfloat16 g_Xlo[Mtot * Dn];           // 32 MB
#define KTOT 3072
__device__ __nv_bfloat16 g_Wsp[512 * KTOT];          // 3 MB: [n][k''], k''=[hi|lo|hi]

__device__ __forceinline__ uint32_t smem_u32(const void* p) {
    uint32_t a;
    asm("{ .reg .u64 t; cvta.to.shared.u64 t, %1; cvt.u32.u64 %0, t; }" : "=r"(a) : "l"(p));
    return a;
}
__device__ __forceinline__ void cp16(uint32_t dst, const void* src) {
    asm volatile("cp.async.cg.shared.global [%0], [%1], 16;" :: "r"(dst), "l"(src));
}
#define CP_COMMIT() asm volatile("cp.async.commit_group;" ::: "memory")
#define CP_WAIT(n)  asm volatile("cp.async.wait_group %0;" :: "n"(n) : "memory")

// ---------------------------------------------------------------------------
// Convert X (fp32) -> bf16 hi/lo
// ---------------------------------------------------------------------------
__global__ void convert_x_kernel(const float* __restrict__ X) {
    int idx = blockIdx.x * blockDim.x + threadIdx.x;     // float4 index
    float4 v = *(const float4*)(X + (size_t)idx * 4);
    __nv_bfloat16 hx = __float2bfloat16(v.x);
    __nv_bfloat16 hy = __float2bfloat16(v.y);
    __nv_bfloat16 hz = __float2bfloat16(v.z);
    __nv_bfloat16 hw = __float2bfloat16(v.w);
    __nv_bfloat162 hp0(hx, hy), hp1(hz, hw);
    __nv_bfloat162 lp0(__float2bfloat16(v.x - __bfloat162float(hx)),
                       __float2bfloat16(v.y - __bfloat162float(hy)));
    __nv_bfloat162 lp1(__float2bfloat16(v.z - __bfloat162float(hz)),
                       __float2bfloat16(v.w - __bfloat162float(hw)));
    *(uint2*)(g_Xhi + (size_t)idx * 4) = make_uint2(*(uint32_t*)&hp0, *(uint32_t*)&hp1);
    *(uint2*)(g_Xlo + (size_t)idx * 4) = make_uint2(*(uint32_t*)&lp0, *(uint32_t*)&lp1);
}

// ---------------------------------------------------------------------------
// Build B'' = [Whi | Wlo | Whi] transposed to [n][k''] (n<256: WQ, else WK)
// ---------------------------------------------------------------------------
__global__ void convert_w_kernel(const float* __restrict__ WQ, const float* __restrict__ WK) {
    int idx = blockIdx.x * blockDim.x + threadIdx.x;     // 0 .. 512*3072-1
    int n  = idx / KTOT;
    int kk = idx - n * KTOT;
    int reg = kk >> 10;            // 0:hi 1:lo 2:hi
    int k   = kk & 1023;
    float x = (n < 256) ? WQ[k * 256 + n] : WK[k * 256 + (n - 256)];
    __nv_bfloat16 hi = __float2bfloat16(x);
    __nv_bfloat16 outv = (reg == 1) ? __float2bfloat16(x - __bfloat162float(hi)) : hi;
    g_Wsp[idx] = outv;
}

// ---------------------------------------------------------------------------
// bf16 mma.sync GEMM, 3-stage cp.async pipeline (R6/R7-proven schedule).
// [Q|K](16384 x 512) over K''=3072. CTA tile 128x128, BK=64, 8 warps (2x4).
// ---------------------------------------------------------------------------
#define BM 128
#define BN 128
#define BK 64
#define PAD 8
#define LDS_A (BK + PAD)          // 72 bf16 = 144 B row stride
#define TILE_E (BM * LDS_A)       // bf16 elems per A/B stage (9216)
#define STG_B  (TILE_E * 2)       // bytes per stage
#define NIT    (KTOT / BK)        // 48
#define NSTG   3
#define SMEM_GEMM (NSTG * 2 * TILE_E * 2)  // 110592 B

__global__ __launch_bounds__(256, 2)
void qk_mma_kernel() {
    extern __shared__ __nv_bfloat16 smg[];
    __nv_bfloat16* As = smg;                      // [NSTG][TILE_E]
    __nv_bfloat16* Bs = smg + NSTG * TILE_E;      // [NSTG][TILE_E]

    const int tid  = threadIdx.x;
    const int wid  = tid >> 5;
    const int lane = tid & 31;
    const int wm = wid & 1;
    const int wn = wid >> 1;
    const int mbase = wm * 64;
    const int nbase = wn * 32;
    const int mtile = blockIdx.y * BM;
    const int ntile = blockIdx.x * BN;

    const int g = lane >> 3;
    const int r = lane & 7;

    float d[4][4][4];
#pragma unroll
    for (int i = 0; i < 4; i++)
#pragma unroll
        for (int j = 0; j < 4; j++)
#pragma unroll
            for (int q = 0; q < 4; q++) d[i][j][q] = 0.f;

    const uint32_t as_base = smem_u32(As);
    const uint32_t bs_base = smem_u32(Bs);

    const int lrow[4] = { (0 * 256 + tid) >> 3, (1 * 256 + tid) >> 3,
                          (2 * 256 + tid) >> 3, (3 * 256 + tid) >> 3 };
    const int lc8 = (tid & 7) * 8;

    auto issue_loads = [&](int it, int s) {
        const int kb = it * BK;
        const __nv_bfloat16* Asrc = (kb < 2048) ? g_Xhi : g_Xlo;
        const int ksrc = kb & 1023;
#pragma unroll
        for (int i = 0; i < 4; i++) {
            int row = lrow[i];
            cp16(as_base + (uint32_t)(s * TILE_E + row * LDS_A + lc8) * 2u,
                 Asrc + (size_t)(mtile + row) * Dn + ksrc + lc8);
        }
#pragma unroll
        for (int i = 0; i < 4; i++) {
            int row = lrow[i];
            cp16(bs_base + (uint32_t)(s * TILE_E + row * LDS_A + lc8) * 2u,
                 g_Wsp + (size_t)(ntile + row) * KTOT + kb + lc8);
        }
        CP_COMMIT();
    };

    issue_loads(0, 0);
    issue_loads(1, 1);

    for (int it = 0; it < NIT; it++) {
        if (it < NIT - 1) { CP_WAIT(1); } else { CP_WAIT(0); }
        __syncthreads();

        const int cur = it % NSTG;
        const uint32_t as_s = as_base + (uint32_t)cur * STG_B;
        const uint32_t bs_s = bs_base + (uint32_t)cur * STG_B;

#pragma unroll
        for (int ks = 0; ks < BK / 16; ks++) {
            const int k0 = ks * 16;
            uint32_t a[4][4];
#pragma unroll
            for (int mf = 0; mf < 4; mf++) {
                int row = mbase + mf * 16 + (g & 1) * 8 + r;
                int col = k0 + (g >> 1) * 8;
                uint32_t addr = as_s + (uint32_t)(row * LDS_A + col) * 2u;
                asm volatile("ldmatrix.sync.aligned.m8n8.x4.shared.b16 {%0,%1,%2,%3}, [%4];"
                             : "=r"(a[mf][0]), "=r"(a[mf][1]), "=r"(a[mf][2]), "=r"(a[mf][3])
                             : "r"(addr));
            }
            uint32_t b[4][2];
#pragma unroll
            for (int nh = 0; nh < 2; nh++) {
                int row = nbase + nh * 16 + (g >> 1) * 8 + r;
                int col = k0 + (g & 1) * 8;
                uint32_t addr = bs_s + (uint32_t)(row * LDS_A + col) * 2u;
                uint32_t t0, t1, t2, t3;
                asm volatile("ldmatrix.sync.aligned.m8n8.x4.shared.b16 {%0,%1,%2,%3}, [%4];"
                             : "=r"(t0), "=r"(t1), "=r"(t2), "=r"(t3) : "r"(addr));
                b[nh * 2 + 0][0] = t0; b[nh * 2 + 0][1] = t1;
                b[nh * 2 + 1][0] = t2; b[nh * 2 + 1][1] = t3;
            }
#pragma unroll
            for (int mf = 0; mf < 4; mf++)
#pragma unroll
                for (int nf = 0; nf < 4; nf++) {
                    asm volatile(
                        "mma.sync.aligned.m16n8k16.row.col.f32.bf16.bf16.f32 "
                        "{%0,%1,%2,%3}, {%4,%5,%6,%7}, {%8,%9}, {%0,%1,%2,%3};"
                        : "+f"(d[mf][nf][0]), "+f"(d[mf][nf][1]),
                          "+f"(d[mf][nf][2]), "+f"(d[mf][nf][3])
                        : "r"(a[mf][0]), "r"(a[mf][1]), "r"(a[mf][2]), "r"(a[mf][3]),
                          "r"(b[nf][0]), "r"(b[nf][1]));
                }
        }

        if (it + 2 < NIT) issue_loads(it + 2, (it + 2) % NSTG);
    }

    float* dst = (ntile < 256) ? g_Q : g_K;
    const int ncol0 = (ntile & 255) + nbase;
#pragma unroll
    for (int mf = 0; mf < 4; mf++) {
#pragma unroll
        for (int nf = 0; nf < 4; nf++) {
            int row = mtile + mbase + mf * 16 + (lane >> 2);
            int col = ncol0 + nf * 8 + (lane & 3) * 2;
            *(float2*)(dst + (size_t)row * DSn + col) =
                make_float2(d[mf][nf][0], d[mf][nf][1]);
            *(float2*)(dst + (size_t)(row + 8) * DSn + col) =
                make_float2(d[mf][nf][2], d[mf][nf][3]);
        }
    }
}

// ---------------------------------------------------------------------------
// P = h @ Wp  (16384 x 1024 @ 1024 x 32), fp32.
// 512 blocks x 256 threads; 32 rows/block, 8 threads/row, 4 k's/thread.
// Wp tiled through smem in [128 x 32] chunks.
// ---------------------------------------------------------------------------
#define PROWS 32
__global__ __launch_bounds__(256)
void p_gemm_kernel(const float* __restrict__ h, const float* __restrict__ Wp) {
    __shared__ float wps[128 * 32];   // 16 KB chunk of Wp

    const int tid = threadIdx.x;
    const int row = blockIdx.x * PROWS + (tid >> 3);
    const int k0  = (tid & 7) * 4;

    float4 acc = make_float4(0.f, 0.f, 0.f, 0.f);

    for (int c = 0; c < 8; c++) {
        // load Wp[c*128 .. +128)[0..32) = 4096 floats: 4 float4 per thread
#pragma unroll
        for (int i = 0; i < 4; i++) {
            int f4 = i * 256 + tid;                  // 0..1023 float4 slots
            *(float4*)&wps[f4 * 4] = *(const float4*)&Wp[c * 128 * 32 + f4 * 4];
        }
        __syncthreads();

        const float4* hrow4 = (const float4*)(h + (size_t)row * Dn + c * 128);
#pragma unroll 8
        for (int j = 0; j < 32; j++) {
            const float4 hv = hrow4[j];
#pragma unroll
            for (int q = 0; q < 4; q++) {
                const float hq = (q == 0) ? hv.x : (q == 1) ? hv.y : (q == 2) ? hv.z : hv.w;
                const float4 wv = *(const float4*)&wps[(j * 4 + q) * 32 + k0];
                acc.x = fmaf(hq, wv.x, acc.x);
                acc.y = fmaf(hq, wv.y, acc.y);
                acc.z = fmaf(hq, wv.z, acc.z);
                acc.w = fmaf(hq, wv.w, acc.w);
            }
        }
        __syncthreads();
    }

    *(float4*)&g_P[(size_t)row * KLn + k0] = acc;
}

// ---------------------------------------------------------------------------
// Stage 2 (band + tiny projection): warp per t, 256 threads, no smem.
//  logits[t][k] = sum_i coef[t][i] * P[t-3+i][k]  -- the ctx never materializes.
// ---------------------------------------------------------------------------
__global__ __launch_bounds__(256)
void band_kernel(const float* __restrict__ tau, float* __restrict__ out) {
    const int b    = blockIdx.y;
    const int t0   = blockIdx.x * 8;
    const int w    = threadIdx.x >> 5;
    const int lane = threadIdx.x & 31;
    const int t    = t0 + w;

    const float inv_tau = 1.0f / tau[0];

    // banded scores + softmax weights
    const float* Qt = g_Q + ((size_t)(b * Tn + t)) * DSn + lane * 8;
    const float4 q0 = *(const float4*)(Qt);
    const float4 q1 = *(const float4*)(Qt + 4);

    float a[7];
#pragma unroll
    for (int i = 0; i < 7; i++) {
        const int s  = t - WINn + i;
        const int sc = min(max(s, 0), Tn - 1);
        const float* Ks = g_K + ((size_t)(b * Tn + sc)) * DSn + lane * 8;
        const float4 k0 = *(const float4*)(Ks);
        const float4 k1 = *(const float4*)(Ks + 4);
        float p = q0.x*k0.x + q0.y*k0.y + q0.z*k0.z + q0.w*k0.w
                + q1.x*k1.x + q1.y*k1.y + q1.z*k1.z + q1.w*k1.w;
#pragma unroll
        for (int off = 16; off; off >>= 1)
            p += __shfl_xor_sync(0xffffffffu, p, off);
        a[i] = (s >= 0 && s < Tn) ? p * (1.0f / 16.0f) : -INFINITY;
    }

    float m = a[0];
#pragma unroll
    for (int i = 1; i < 7; i++) m = fmaxf(m, a[i]);
    float sum = 0.f;
#pragma unroll
    for (int i = 0; i < 7; i++) { a[i] = expf(a[i] - m); sum += a[i]; }
    const float inv = 1.0f / sum;

    // logit[k=lane] = sum_i coef_i * P[s_i][lane]
    float logit = 0.f;
#pragma unroll
    for (int i = 0; i < 7; i++) {
        const int sc = min(max(t - WINn + i, 0), Tn - 1);
        const float pv = g_P[((size_t)(b * Tn + sc)) * KLn + lane];   // coalesced 128B
        logit = fmaf(a[i] * inv, pv, logit);
    }
    logit *= inv_tau;

    // softmax over k = lane
    float mm = logit;
#pragma unroll
    for (int off = 16; off; off >>= 1)
        mm = fmaxf(mm, __shfl_xor_sync(0xffffffffu, mm, off));
    const float e = expf(logit - mm);
    float ss = e;
#pragma unroll
    for (int off = 16; off; off >>= 1)
        ss += __shfl_xor_sync(0xffffffffu, ss, off);

    out[((size_t)(b * Tn + t)) * KLn + lane] = e / ss;
}

// ----------------------------------------------------------------------------
// Launch
// ----------------------------------------------------------------------------
extern "C" void kernel_launch(void* const* d_in, const int* in_sizes, int n_in,
                              void* d_out, int out_size)
{
    const float* h   = (const float*)d_in[0];
    const float* tau = (const float*)d_in[1];
    const float* WQ  = (const float*)d_in[2];
    const float* WK  = (const float*)d_in[3];
    const float* Wp  = (const float*)d_in[4];
    float* out = (float*)d_out;

    cudaFuncSetAttribute(qk_mma_kernel,
                         cudaFuncAttributeMaxDynamicSharedMemorySize, SMEM_GEMM);

    convert_x_kernel<<<(Mtot * Dn / 4) / 256, 256>>>(h);
    convert_w_kernel<<<(512 * KTOT) / 256, 256>>>(WQ, WK);

    dim3 g1(512 / BN, Mtot / BM);      // (4, 128)
    qk_mma_kernel<<<g1, 256, SMEM_GEMM>>>();

    p_gemm_kernel<<<Mtot / PROWS, 256>>>(h, Wp);

    dim3 g2(Tn / 8, Bn);               // (256, 8)
    band_kernel<<<g2, 256>>>(tau, out);
}

// round 16
// speedup vs baseline: 1.2313x; 1.2313x over previous
#include <cuda_runtime.h>
#include <cuda_bf16.h>
#include <math.h>
#include <stdint.h>

// Problem constants
#define Bn    8
#define Tn    2048
#define Dn    1024
#define DSn   256
#define KLn   32
#define WINn  3
#define Mtot  (Bn * Tn)      // 16384
// SCALE = sqrt(DS) = 16

// Output-column layout of the fused GEMM: [Q(256) | K(256) | P(32) | pad(96)]
#define NOUT  640

// Scratch
__device__ float g_Q[Mtot * DSn];                    // 16 MB
__device__ float g_K[Mtot * DSn];                    // 16 MB
__device__ float g_P[Mtot * KLn];                    // 2 MB:  P = h @ Wp
__device__ __nv_bfloat16 g_Xhi[Mtot * Dn];           // 32 MB
__device__ __nv_bfloat16 g_Xlo[Mtot * Dn];           // 32 MB
#define KTOT 3072
__device__ __nv_bfloat16 g_Wsp[NOUT * KTOT];         // 3.75 MB: [n][k''], k''=[hi|lo|hi]

__device__ __forceinline__ uint32_t smem_u32(const void* p) {
    uint32_t a;
    asm("{ .reg .u64 t; cvta.to.shared.u64 t, %1; cvt.u32.u64 %0, t; }" : "=r"(a) : "l"(p));
    return a;
}
__device__ __forceinline__ void cp16(uint32_t dst, const void* src) {
    asm volatile("cp.async.cg.shared.global [%0], [%1], 16;" :: "r"(dst), "l"(src));
}
#define CP_COMMIT() asm volatile("cp.async.commit_group;" ::: "memory")
#define CP_WAIT(n)  asm volatile("cp.async.wait_group %0;" :: "n"(n) : "memory")

// ---------------------------------------------------------------------------
// Convert X (fp32) -> bf16 hi/lo
// ---------------------------------------------------------------------------
__global__ void convert_x_kernel(const float* __restrict__ X) {
    int idx = blockIdx.x * blockDim.x + threadIdx.x;     // float4 index
    float4 v = *(const float4*)(X + (size_t)idx * 4);
    __nv_bfloat16 hx = __float2bfloat16(v.x);
    __nv_bfloat16 hy = __float2bfloat16(v.y);
    __nv_bfloat16 hz = __float2bfloat16(v.z);
    __nv_bfloat16 hw = __float2bfloat16(v.w);
    __nv_bfloat162 hp0(hx, hy), hp1(hz, hw);
    __nv_bfloat162 lp0(__float2bfloat16(v.x - __bfloat162float(hx)),
                       __float2bfloat16(v.y - __bfloat162float(hy)));
    __nv_bfloat162 lp1(__float2bfloat16(v.z - __bfloat162float(hz)),
                       __float2bfloat16(v.w - __bfloat162float(hw)));
    *(uint2*)(g_Xhi + (size_t)idx * 4) = make_uint2(*(uint32_t*)&hp0, *(uint32_t*)&hp1);
    *(uint2*)(g_Xlo + (size_t)idx * 4) = make_uint2(*(uint32_t*)&lp0, *(uint32_t*)&lp1);
}

// ---------------------------------------------------------------------------
// Build B'' = [hi | lo | hi] of [WQ | WK | Wp | 0], transposed to [n][k''].
// n<256: WQ col n ; n<512: WK col n-256 ; n<544: Wp col n-512 ; else zero.
// ---------------------------------------------------------------------------
__global__ void convert_w_kernel(const float* __restrict__ WQ,
                                 const float* __restrict__ WK,
                                 const float* __restrict__ Wp) {
    int idx = blockIdx.x * blockDim.x + threadIdx.x;     // 0 .. NOUT*KTOT-1
    int n  = idx / KTOT;
    int kk = idx - n * KTOT;
    int reg = kk >> 10;            // 0:hi 1:lo 2:hi
    int k   = kk & 1023;
    float x;
    if (n < 256)       x = WQ[k * 256 + n];
    else if (n < 512)  x = WK[k * 256 + (n - 256)];
    else if (n < 544)  x = Wp[k * KLn + (n - 512)];
    else               x = 0.f;
    __nv_bfloat16 hi = __float2bfloat16(x);
    __nv_bfloat16 outv = (reg == 1) ? __float2bfloat16(x - __bfloat162float(hi)) : hi;
    g_Wsp[idx] = outv;
}

// ---------------------------------------------------------------------------
// bf16 mma.sync GEMM, 3-stage cp.async pipeline (R6/R7-proven schedule).
// [Q|K|P](16384 x 640) over K''=3072. CTA tile 128x128, BK=64, 8 warps (2x4).
// ---------------------------------------------------------------------------
#define BM 128
#define BN 128
#define BK 64
#define PAD 8
#define LDS_A (BK + PAD)          // 72 bf16 = 144 B row stride
#define TILE_E (BM * LDS_A)       // bf16 elems per A/B stage (9216)
#define STG_B  (TILE_E * 2)       // bytes per stage
#define NIT    (KTOT / BK)        // 48
#define NSTG   3
#define SMEM_GEMM (NSTG * 2 * TILE_E * 2)  // 110592 B

__global__ __launch_bounds__(256, 2)
void qk_mma_kernel() {
    extern __shared__ __nv_bfloat16 smg[];
    __nv_bfloat16* As = smg;                      // [NSTG][TILE_E]
    __nv_bfloat16* Bs = smg + NSTG * TILE_E;      // [NSTG][TILE_E]

    const int tid  = threadIdx.x;
    const int wid  = tid >> 5;
    const int lane = tid & 31;
    const int wm = wid & 1;
    const int wn = wid >> 1;
    const int mbase = wm * 64;
    const int nbase = wn * 32;
    const int mtile = blockIdx.y * BM;
    const int ntile = blockIdx.x * BN;

    const int g = lane >> 3;
    const int r = lane & 7;

    float d[4][4][4];
#pragma unroll
    for (int i = 0; i < 4; i++)
#pragma unroll
        for (int j = 0; j < 4; j++)
#pragma unroll
            for (int q = 0; q < 4; q++) d[i][j][q] = 0.f;

    const uint32_t as_base = smem_u32(As);
    const uint32_t bs_base = smem_u32(Bs);

    const int lrow[4] = { (0 * 256 + tid) >> 3, (1 * 256 + tid) >> 3,
                          (2 * 256 + tid) >> 3, (3 * 256 + tid) >> 3 };
    const int lc8 = (tid & 7) * 8;

    auto issue_loads = [&](int it, int s) {
        const int kb = it * BK;
        const __nv_bfloat16* Asrc = (kb < 2048) ? g_Xhi : g_Xlo;
        const int ksrc = kb & 1023;
#pragma unroll
        for (int i = 0; i < 4; i++) {
            int row = lrow[i];
            cp16(as_base + (uint32_t)(s * TILE_E + row * LDS_A + lc8) * 2u,
                 Asrc + (size_t)(mtile + row) * Dn + ksrc + lc8);
        }
#pragma unroll
        for (int i = 0; i < 4; i++) {
            int row = lrow[i];
            cp16(bs_base + (uint32_t)(s * TILE_E + row * LDS_A + lc8) * 2u,
                 g_Wsp + (size_t)(ntile + row) * KTOT + kb + lc8);
        }
        CP_COMMIT();
    };

    issue_loads(0, 0);
    issue_loads(1, 1);

    for (int it = 0; it < NIT; it++) {
        if (it < NIT - 1) { CP_WAIT(1); } else { CP_WAIT(0); }
        __syncthreads();

        const int cur = it % NSTG;
        const uint32_t as_s = as_base + (uint32_t)cur * STG_B;
        const uint32_t bs_s = bs_base + (uint32_t)cur * STG_B;

#pragma unroll
        for (int ks = 0; ks < BK / 16; ks++) {
            const int k0 = ks * 16;
            uint32_t a[4][4];
#pragma unroll
            for (int mf = 0; mf < 4; mf++) {
                int row = mbase + mf * 16 + (g & 1) * 8 + r;
                int col = k0 + (g >> 1) * 8;
                uint32_t addr = as_s + (uint32_t)(row * LDS_A + col) * 2u;
                asm volatile("ldmatrix.sync.aligned.m8n8.x4.shared.b16 {%0,%1,%2,%3}, [%4];"
                             : "=r"(a[mf][0]), "=r"(a[mf][1]), "=r"(a[mf][2]), "=r"(a[mf][3])
                             : "r"(addr));
            }
            uint32_t b[4][2];
#pragma unroll
            for (int nh = 0; nh < 2; nh++) {
                int row = nbase + nh * 16 + (g >> 1) * 8 + r;
                int col = k0 + (g & 1) * 8;
                uint32_t addr = bs_s + (uint32_t)(row * LDS_A + col) * 2u;
                uint32_t t0, t1, t2, t3;
                asm volatile("ldmatrix.sync.aligned.m8n8.x4.shared.b16 {%0,%1,%2,%3}, [%4];"
                             : "=r"(t0), "=r"(t1), "=r"(t2), "=r"(t3) : "r"(addr));
                b[nh * 2 + 0][0] = t0; b[nh * 2 + 0][1] = t1;
                b[nh * 2 + 1][0] = t2; b[nh * 2 + 1][1] = t3;
            }
#pragma unroll
            for (int mf = 0; mf < 4; mf++)
#pragma unroll
                for (int nf = 0; nf < 4; nf++) {
                    asm volatile(
                        "mma.sync.aligned.m16n8k16.row.col.f32.bf16.bf16.f32 "
                        "{%0,%1,%2,%3}, {%4,%5,%6,%7}, {%8,%9}, {%0,%1,%2,%3};"
                        : "+f"(d[mf][nf][0]), "+f"(d[mf][nf][1]),
                          "+f"(d[mf][nf][2]), "+f"(d[mf][nf][3])
                        : "r"(a[mf][0]), "r"(a[mf][1]), "r"(a[mf][2]), "r"(a[mf][3]),
                          "r"(b[nf][0]), "r"(b[nf][1]));
                }
        }

        if (it + 2 < NIT) issue_loads(it + 2, (it + 2) % NSTG);
    }

    if (ntile < 512) {
        // Q / K tiles (unchanged proven epilogue)
        float* dst = (ntile < 256) ? g_Q : g_K;
        const int ncol0 = (ntile & 255) + nbase;
#pragma unroll
        for (int mf = 0; mf < 4; mf++) {
#pragma unroll
            for (int nf = 0; nf < 4; nf++) {
                int row = mtile + mbase + mf * 16 + (lane >> 2);
                int col = ncol0 + nf * 8 + (lane & 3) * 2;
                *(float2*)(dst + (size_t)row * DSn + col) =
                    make_float2(d[mf][nf][0], d[mf][nf][1]);
                *(float2*)(dst + (size_t)(row + 8) * DSn + col) =
                    make_float2(d[mf][nf][2], d[mf][nf][3]);
            }
        }
    } else if (wn == 0) {
        // P tile: only warp-columns 0..31 are valid (cols 32..127 are zero pad)
#pragma unroll
        for (int mf = 0; mf < 4; mf++) {
#pragma unroll
            for (int nf = 0; nf < 4; nf++) {
                int row = mtile + mbase + mf * 16 + (lane >> 2);
                int col = nf * 8 + (lane & 3) * 2;          // 0..31
                *(float2*)(g_P + (size_t)row * KLn + col) =
                    make_float2(d[mf][nf][0], d[mf][nf][1]);
                *(float2*)(g_P + (size_t)(row + 8) * KLn + col) =
                    make_float2(d[mf][nf][2], d[mf][nf][3]);
            }
        }
    }
}

// ---------------------------------------------------------------------------
// Stage 2 (band + tiny projection): warp per t, 256 threads, no smem.
//  logits[t][k] = sum_i coef[t][i] * P[t-3+i][k]  -- the ctx never materializes.
// ---------------------------------------------------------------------------
__global__ __launch_bounds__(256)
void band_kernel(const float* __restrict__ tau, float* __restrict__ out) {
    const int b    = blockIdx.y;
    const int t0   = blockIdx.x * 8;
    const int w    = threadIdx.x >> 5;
    const int lane = threadIdx.x & 31;
    const int t    = t0 + w;

    const float inv_tau = 1.0f / tau[0];

    // banded scores + softmax weights
    const float* Qt = g_Q + ((size_t)(b * Tn + t)) * DSn + lane * 8;
    const float4 q0 = *(const float4*)(Qt);
    const float4 q1 = *(const float4*)(Qt + 4);

    float a[7];
#pragma unroll
    for (int i = 0; i < 7; i++) {
        const int s  = t - WINn + i;
        const int sc = min(max(s, 0), Tn - 1);
        const float* Ks = g_K + ((size_t)(b * Tn + sc)) * DSn + lane * 8;
        const float4 k0 = *(const float4*)(Ks);
        const float4 k1 = *(const float4*)(Ks + 4);
        float p = q0.x*k0.x + q0.y*k0.y + q0.z*k0.z + q0.w*k0.w
                + q1.x*k1.x + q1.y*k1.y + q1.z*k1.z + q1.w*k1.w;
#pragma unroll
        for (int off = 16; off; off >>= 1)
            p += __shfl_xor_sync(0xffffffffu, p, off);
        a[i] = (s >= 0 && s < Tn) ? p * (1.0f / 16.0f) : -INFINITY;
    }

    float m = a[0];
#pragma unroll
    for (int i = 1; i < 7; i++) m = fmaxf(m, a[i]);
    float sum = 0.f;
#pragma unroll
    for (int i = 0; i < 7; i++) { a[i] = expf(a[i] - m); sum += a[i]; }
    const float inv = 1.0f / sum;

    // logit[k=lane] = sum_i coef_i * P[s_i][lane]
    float logit = 0.f;
#pragma unroll
    for (int i = 0; i < 7; i++) {
        const int sc = min(max(t - WINn + i, 0), Tn - 1);
        const float pv = g_P[((size_t)(b * Tn + sc)) * KLn + lane];   // coalesced 128B
        logit = fmaf(a[i] * inv, pv, logit);
    }
    logit *= inv_tau;

    // softmax over k = lane
    float mm = logit;
#pragma unroll
    for (int off = 16; off; off >>= 1)
        mm = fmaxf(mm, __shfl_xor_sync(0xffffffffu, mm, off));
    const float e = expf(logit - mm);
    float ss = e;
#pragma unroll
    for (int off = 16; off; off >>= 1)
        ss += __shfl_xor_sync(0xffffffffu, ss, off);

    out[((size_t)(b * Tn + t)) * KLn + lane] = e / ss;
}

// ----------------------------------------------------------------------------
// Launch
// ----------------------------------------------------------------------------
extern "C" void kernel_launch(void* const* d_in, const int* in_sizes, int n_in,
                              void* d_out, int out_size)
{
    const float* h   = (const float*)d_in[0];
    const float* tau = (const float*)d_in[1];
    const float* WQ  = (const float*)d_in[2];
    const float* WK  = (const float*)d_in[3];
    const float* Wp  = (const float*)d_in[4];
    float* out = (float*)d_out;

    cudaFuncSetAttribute(qk_mma_kernel,
                         cudaFuncAttributeMaxDynamicSharedMemorySize, SMEM_GEMM);

    convert_x_kernel<<<(Mtot * Dn / 4) / 256, 256>>>(h);
    convert_w_kernel<<<(NOUT * KTOT) / 256, 256>>>(WQ, WK, Wp);

    dim3 g1(NOUT / BN, Mtot / BM);     // (5, 128)
    qk_mma_kernel<<<g1, 256, SMEM_GEMM>>>();

    dim3 g2(Tn / 8, Bn);               // (256, 8)
    band_kernel<<<g2, 256>>>(tau, out);
}